// round 3
// baseline (speedup 1.0000x reference)
#include <cuda_runtime.h>
#include <math.h>

#define K 128
#define E 4096
#define M 512
#define NUM_UPDATE 3
#define THRESHOLD 0.05f
#define ECHUNK 256
#define NCHUNK (E / ECHUNK)   // 16
#define MAXNZ 32

// ---------------- device scratch ----------------
__device__ unsigned char g_nzpk[E * MAXNZ];  // packed byte indices, row e at e*32
__device__ int   g_nzcnt[E];
__device__ float g_Ic[E];
__device__ float g_bz[E];                 // beta2[e] * Zc[e]
__device__ float g_uw[K * E];             // user * W
__device__ float g_u[K];
__device__ float g_dv[K];
__device__ float g_partial[K * NCHUNK];
__device__ int   g_upd[K];
__device__ unsigned g_done[NUM_UPDATE];

// ---------------- init: nz byte-pack, bz, uw, u0, upd, counters ----------------
// grid = E/8 = 512 blocks of 256
__global__ void init_kernel(const float* __restrict__ q_kn,
                            const float* __restrict__ U,
                            const int* __restrict__ stu_id,
                            const int* __restrict__ kn_id,
                            const float* __restrict__ gamma_c,
                            const float* __restrict__ d,
                            const float* __restrict__ score,
                            const float* __restrict__ beta2,
                            const float* __restrict__ W,
                            const float* __restrict__ user) {
    int tid = threadIdx.x;
    int w = tid >> 5, l = tid & 31;
    int e = blockIdx.x * 8 + w;

    int base = 0;
#pragma unroll
    for (int r = 0; r < 4; r++) {
        int j = r * 32 + l;
        float q = q_kn[(size_t)e * K + j];
        unsigned m = __ballot_sync(0xFFFFFFFFu, q != 0.0f);
        if (q != 0.0f) {
            int pos = base + __popc(m & ((1u << l) - 1u));
            if (pos < MAXNZ) g_nzpk[e * MAXNZ + pos] = (unsigned char)j;
        }
        base += __popc(m);
    }
    if (l == 0) {
        g_nzcnt[e] = base < MAXNZ ? base : MAXNZ;
        // Zc = sigmoid(-(gamma_c/d)*(sc-0.5)) - 0.5
        float x = (gamma_c[e] / d[e]) * (score[e] - 0.5f);
        g_bz[e] = beta2[e] * (1.0f / (1.0f + expf(x)) - 0.5f);
    }

    // uw = user * W, grid-stride: 512*256 threads cover K*E = 524288 -> 4 each
    int gt = blockIdx.x * 256 + tid;
    for (int i = gt; i < K * E; i += 512 * 256) g_uw[i] = user[i] * W[i];

    if (blockIdx.x == 0) {
        if (tid < NUM_UPDATE) g_done[tid] = 0u;
        if (tid < K) {
            g_u[tid]   = U[stu_id[0] * K + tid];
            g_upd[tid] = 0;
        }
        __syncthreads();
        if (tid < K) {
            int kn = kn_id[tid];
            if (kn >= 0 && kn < K) g_upd[kn] = 1;
        }
    }
}

// ---------------- per-step prologue: dv, su (sparse), Ic ----------------
// grid = E/256 = 16 blocks of 256
__global__ void pre_kernel(const float* __restrict__ d,
                           const float* __restrict__ score,
                           const float* __restrict__ gs,
                           const float* __restrict__ A_emb) {
    __shared__ float s_u[K];
    int tid = threadIdx.x;
    if (tid < K) s_u[tid] = g_u[tid];
    __syncthreads();

    int e = blockIdx.x * 256 + tid;
    int cnt = g_nzcnt[e];
    unsigned wv[8];
    *(uint4*)wv       = *(const uint4*)(g_nzpk + e * MAXNZ);
    if (cnt > 16) *(uint4*)(wv + 4) = *(const uint4*)(g_nzpk + e * MAXNZ + 16);
    float su = 0.0f;
    for (int i = 0; i < cnt; i++) {
        int j = (wv[i >> 2] >> ((i & 3) * 8)) & 0xFF;
        su += s_u[j];
    }
    float t  = score[e] - su / d[e];
    float yc = expf(-t * t);
    float ic = A_emb[3 * e + 0] * (1.0f - gs[2 * e + 0])
             + A_emb[3 * e + 1] * (1.0f - gs[2 * e + 1])
             + A_emb[3 * e + 2] * yc;
    g_Ic[e] = 1.0f / (1.0f + expf(ic));

    if (blockIdx.x == 0 && tid < K) {
        float dv = s_u[tid] - 0.5f;
        g_dv[tid] = (fabsf(dv) > THRESHOLD) ? dv : 0.0f;
    }
}

// ---------------- fused big kernel: sparse gather + epilogue in last block ----------------
// grid = (NCHUNK, K) = 2048 blocks of 256; thread -> (k, e)
__global__ __launch_bounds__(256) void big_kernel(const float* __restrict__ Bm,
                                                  const float* __restrict__ beta1,
                                                  float* __restrict__ out,
                                                  int step) {
    int k = blockIdx.y;
    int tid = threadIdx.x;
    int e = blockIdx.x * ECHUNK + tid;

    __shared__ float s_dv[K];
    if (tid < K) s_dv[tid] = g_dv[tid];
    __syncthreads();

    int cnt = g_nzcnt[e];
    unsigned wv[8];
    *(uint4*)wv       = *(const uint4*)(g_nzpk + e * MAXNZ);
    if (cnt > 16) *(uint4*)(wv + 4) = *(const uint4*)(g_nzpk + e * MAXNZ + 16);

    const float* __restrict__ Brow = Bm + ((size_t)k * E + e) * K;
    float dot = 0.0f;
    for (int i = 0; i < cnt; i++) {
        int j = (wv[i >> 2] >> ((i & 3) * 8)) & 0xFF;
        if (j != k) dot += __ldg(Brow + j) * s_dv[j];
    }

    // Gkc = sigmoid(-Gsum) - 1 ; WK = Ic*(beta1*Gkc + bz) ; v = uw * WK
    float gkc = 1.0f / (1.0f + expf(dot)) - 1.0f;
    float wk  = g_Ic[e] * (beta1[(size_t)k * E + e] * gkc + g_bz[e]);
    float v   = g_uw[(size_t)k * E + e] * wk;

    // deterministic block reduction
    __shared__ float warpacc[8];
    int w = tid >> 5, l = tid & 31;
    v += __shfl_xor_sync(0xFFFFFFFFu, v, 16);
    v += __shfl_xor_sync(0xFFFFFFFFu, v, 8);
    v += __shfl_xor_sync(0xFFFFFFFFu, v, 4);
    v += __shfl_xor_sync(0xFFFFFFFFu, v, 2);
    v += __shfl_xor_sync(0xFFFFFFFFu, v, 1);
    if (l == 0) warpacc[w] = v;
    __syncthreads();

    __shared__ bool is_last;
    if (tid == 0) {
        float s = 0.0f;
#pragma unroll
        for (int i = 0; i < 8; i++) s += warpacc[i];
        g_partial[k * NCHUNK + blockIdx.x] = s;
        __threadfence();
        unsigned t = atomicAdd(&g_done[step], 1u);
        is_last = (t == (unsigned)(NCHUNK * K - 1));
    }
    __syncthreads();

    if (!is_last) return;
    __threadfence();

    // ---- fused epilogue (one block) ----
    __shared__ float red[K];
    float dd = 0.0f;
    if (tid < K) {
        float s = 0.0f;
#pragma unroll
        for (int c = 0; c < NCHUNK; c++) s += g_partial[tid * NCHUNK + c];
        float u_old = g_u[tid];
        float u_new = 1.0f / (1.0f + expf(s));   // sigmoid(-s)
        float un = g_upd[tid] ? u_new : u_old;
        dd = un - u_old;
        g_u[tid] = un;
        if (step == NUM_UPDATE - 2) out[K + tid] = un;  // state_2nd_last
        if (step == NUM_UPDATE - 1) out[tid]     = un;  // state_last
        red[tid] = dd * dd;
    }
    __syncthreads();
    if (tid < K) {
#pragma unroll
        for (int off = 64; off > 0; off >>= 1) {
            if (tid < off) red[tid] += red[tid + off];
            __syncthreads();
        }
    }
    if (tid == 0) out[2 * K + M + step] = sqrtf(red[0]);
}

// ---------------- final predict ----------------
__global__ void predict_kernel(const float* __restrict__ d,
                               const float* __restrict__ alpha,
                               const float* __restrict__ gamma_e,
                               const int* __restrict__ ex_id,
                               float* __restrict__ out) {
    __shared__ float s_u[K];
    int tid = threadIdx.x;
    if (tid < K) s_u[tid] = g_u[tid];
    __syncthreads();

    int m = blockIdx.x * 256 + tid;
    if (m < M) {
        int e = ex_id[m];
        int cnt = g_nzcnt[e];
        unsigned wv[8];
        *(uint4*)wv       = *(const uint4*)(g_nzpk + e * MAXNZ);
        if (cnt > 16) *(uint4*)(wv + 4) = *(const uint4*)(g_nzpk + e * MAXNZ + 16);
        float acc = 0.0f;
        for (int i = 0; i < cnt; i++) {
            int j = (wv[i >> 2] >> ((i & 3) * 8)) & 0xFF;
            acc += s_u[j];
        }
        float Ukse = acc / d[e] - 0.5f;
        out[2 * K + m] = 1.0f / (1.0f + expf(alpha[e] * Ukse + gamma_e[e]));
    }
}

// ---------------- launch ----------------
extern "C" void kernel_launch(void* const* d_in, const int* in_sizes, int n_in,
                              void* d_out, int out_size) {
    const float* U       = (const float*)d_in[0];   // (S,K)
    const float* W       = (const float*)d_in[1];   // (K,E)
    const float* beta1   = (const float*)d_in[2];   // (K,E)
    const float* beta2   = (const float*)d_in[3];   // (E,1)
    const float* Bm      = (const float*)d_in[4];   // (K,E,K)
    const float* gs      = (const float*)d_in[5];   // (E,2)
    const float* A_emb   = (const float*)d_in[6];   // (E,3)
    const float* gamma_c = (const float*)d_in[7];   // (E,1)
    const float* gamma_e = (const float*)d_in[8];   // (E,1)
    const float* alpha   = (const float*)d_in[9];   // (E,1)
    const float* score   = (const float*)d_in[10];  // (E,1)
    const float* user    = (const float*)d_in[11];  // (K,E)
    const float* q_kn    = (const float*)d_in[12];  // (E,K)
    const float* d       = (const float*)d_in[13];  // (E,1)
    const int*   stu_id  = (const int*)d_in[14];    // scalar
    const int*   kn_id   = (const int*)d_in[15];    // (K,)
    const int*   ex_id   = (const int*)d_in[16];    // (M,)
    float* out = (float*)d_out;

    init_kernel<<<E / 8, 256>>>(q_kn, U, stu_id, kn_id, gamma_c, d, score,
                                beta2, W, user);
    for (int step = 0; step < NUM_UPDATE; ++step) {
        pre_kernel<<<E / 256, 256>>>(d, score, gs, A_emb);
        big_kernel<<<dim3(NCHUNK, K), 256>>>(Bm, beta1, out, step);
    }
    predict_kernel<<<(M + 255) / 256, 256>>>(d, alpha, gamma_e, ex_id, out);
}

// round 4
// speedup vs baseline: 1.0666x; 1.0666x over previous
#include <cuda_runtime.h>
#include <math.h>

#define K 128
#define E 4096
#define M 512
#define NUM_UPDATE 3
#define THRESHOLD 0.05f
#define HOT 8
#define MAXNZ 32
#define NBLK 4            // e-chunks in big grid
#define EPB 1024          // e per block (4 per thread, 256 threads)

// ---------------- device scratch ----------------
__device__ __align__(16) unsigned char g_nzpk[E * MAXNZ];
__device__ unsigned char g_cnt[E];
__device__ float2 g_icbz[E];                  // (Ic, beta2*Zc) per e, Ic refreshed per step
__device__ float  g_bz[E];
__device__ float2 g_buw[(size_t)K * E];       // (beta1, user*W)
__device__ float  g_Bc[(size_t)K * E * HOT];  // gathered B, diag/pad zeroed (16.8 MB)
__device__ __align__(16) float g_dval[E * HOT]; // dv[j_i(e)] per step
__device__ float  g_dv[K];
__device__ float  g_u[K];
__device__ int    g_upd[K];
__device__ float  g_partial[K * NBLK];
__device__ unsigned g_done[NUM_UPDATE];

__device__ __forceinline__ float sigm_neg(float x) {
    // sigmoid(-x) = 1/(1+e^x)
    return __fdividef(1.0f, 1.0f + __expf(x));
}

// ---------------- init0: nz lists, dval0, Ic0, bz, buw, u0 ----------------
// grid = E/8 = 512 blocks of 256 (warp per e) + grid-stride buw fill
__global__ void init0_kernel(const float* __restrict__ q_kn,
                             const float* __restrict__ U,
                             const int* __restrict__ stu_id,
                             const int* __restrict__ kn_id,
                             const float* __restrict__ gamma_c,
                             const float* __restrict__ dd,
                             const float* __restrict__ score,
                             const float* __restrict__ beta2,
                             const float* __restrict__ W,
                             const float* __restrict__ user,
                             const float* __restrict__ gs,
                             const float* __restrict__ A_emb) {
    int tid = threadIdx.x;
    int w = tid >> 5, l = tid & 31;
    int e = blockIdx.x * 8 + w;
    int stu = stu_id[0];

    if (l < HOT) g_dval[e * HOT + l] = 0.0f;
    __syncwarp();

    int base = 0;
    float su = 0.0f;
#pragma unroll
    for (int r = 0; r < 4; r++) {
        int j = r * 32 + l;
        float q = q_kn[(size_t)e * K + j];
        unsigned m = __ballot_sync(0xFFFFFFFFu, q != 0.0f);
        if (q != 0.0f) {
            int pos = base + __popc(m & ((1u << l) - 1u));
            float u0j = U[(size_t)stu * K + j];
            if (pos < MAXNZ) g_nzpk[e * MAXNZ + pos] = (unsigned char)j;
            float dvj = u0j - 0.5f;
            dvj = (fabsf(dvj) > THRESHOLD) ? dvj : 0.0f;
            if (pos < HOT) g_dval[e * HOT + pos] = dvj;
            su += u0j;
        }
        base += __popc(m);
    }
    su += __shfl_xor_sync(0xFFFFFFFFu, su, 16);
    su += __shfl_xor_sync(0xFFFFFFFFu, su, 8);
    su += __shfl_xor_sync(0xFFFFFFFFu, su, 4);
    su += __shfl_xor_sync(0xFFFFFFFFu, su, 2);
    su += __shfl_xor_sync(0xFFFFFFFFu, su, 1);
    if (l == 0) {
        g_cnt[e] = (unsigned char)(base < MAXNZ ? base : MAXNZ);
        float x  = (gamma_c[e] / dd[e]) * (score[e] - 0.5f);
        float bz = beta2[e] * (sigm_neg(x) - 0.5f);
        g_bz[e] = bz;
        float t  = score[e] - su / dd[e];
        float yc = __expf(-t * t);
        float ic = A_emb[3 * e + 0] * (1.0f - gs[2 * e + 0])
                 + A_emb[3 * e + 1] * (1.0f - gs[2 * e + 1])
                 + A_emb[3 * e + 2] * yc;
        g_icbz[e] = make_float2(sigm_neg(ic), bz);
    }

    // buw = (beta1 ... done below), fill (beta1,u*W) grid-stride
    // beta1 passed via W? no: handled in init0b — do it here with extra params:
    // (we reuse gs/A_emb slots? no) -> separate loop with pointers passed:
    // NOTE: beta1 comes through the 'user' path in init0b below.

    if (blockIdx.x == 0) {
        if (tid < NUM_UPDATE) g_done[tid] = 0u;
        if (tid < K) {
            float u0 = U[(size_t)stu * K + tid];
            g_u[tid] = u0;
            float dv = u0 - 0.5f;
            g_dv[tid] = (fabsf(dv) > THRESHOLD) ? dv : 0.0f;
            g_upd[tid] = 0;
        }
        __syncthreads();
        if (tid < K) {
            int kn = kn_id[tid];
            if (kn >= 0 && kn < K) g_upd[kn] = 1;
        }
    }
}

// buw fill: grid-stride, separate tiny kernel (fully parallel, overlaps nothing but cheap)
__global__ void init0b_kernel(const float* __restrict__ beta1,
                              const float* __restrict__ W,
                              const float* __restrict__ user) {
    int i = blockIdx.x * blockDim.x + threadIdx.x;
    for (; i < K * E; i += gridDim.x * blockDim.x)
        g_buw[i] = make_float2(beta1[i], user[i] * W[i]);
}

// ---------------- init1: build Bc (one-time scattered gather) ----------------
// grid = (NBLK, K), 256 threads, 4 e's per thread
__global__ __launch_bounds__(256) void init1_kernel(const float* __restrict__ Bm) {
    int k = blockIdx.y;
    size_t kE = (size_t)k * E;
    int tid = threadIdx.x;
#pragma unroll
    for (int r = 0; r < 4; r++) {
        int e = blockIdx.x * EPB + r * 256 + tid;
        uint2 pk = *(const uint2*)(g_nzpk + e * MAXNZ);
        int cnt = g_cnt[e];
        const float* __restrict__ Brow = Bm + (kE + e) * K;
        unsigned pw[2] = {pk.x, pk.y};
        float v[HOT];
#pragma unroll
        for (int i = 0; i < HOT; i++) {
            int j = (pw[i >> 2] >> ((i & 3) * 8)) & 0xFF;
            v[i] = (i < cnt && j != k) ? __ldg(Brow + j) : 0.0f;
        }
        float4* dst = (float4*)(g_Bc + (kE + e) * HOT);
        dst[0] = make_float4(v[0], v[1], v[2], v[3]);
        dst[1] = make_float4(v[4], v[5], v[6], v[7]);
    }
}

// ---------------- big step kernel (fused epilogue in last block) ----------------
// grid = (NBLK, K), 256 threads, 4 e's per thread
__global__ __launch_bounds__(256) void big_kernel(const float* __restrict__ Bm,
                                                  const float* __restrict__ dd,
                                                  const float* __restrict__ score,
                                                  const float* __restrict__ gs,
                                                  const float* __restrict__ A_emb,
                                                  float* __restrict__ out,
                                                  int step) {
    int k = blockIdx.y;
    size_t kE = (size_t)k * E;
    int tid = threadIdx.x;
    float acc = 0.0f;

#pragma unroll
    for (int r = 0; r < 4; r++) {
        int e = blockIdx.x * EPB + r * 256 + tid;
        const float4* bc = (const float4*)(g_Bc + (kE + e) * HOT);
        float4 b0 = bc[0], b1 = bc[1];
        const float4* dp = (const float4*)(g_dval + e * HOT);
        float4 d0 = dp[0], d1 = dp[1];
        float dot = b0.x * d0.x + b0.y * d0.y + b0.z * d0.z + b0.w * d0.w
                  + b1.x * d1.x + b1.y * d1.y + b1.z * d1.z + b1.w * d1.w;
        int cnt = g_cnt[e];
        if (cnt > HOT) {  // rare (~2% of e rows)
            const uint4* pkp = (const uint4*)(g_nzpk + e * MAXNZ);
            uint4 p0 = pkp[0], p1 = pkp[1];
            unsigned pw[8] = {p0.x, p0.y, p0.z, p0.w, p1.x, p1.y, p1.z, p1.w};
            const float* __restrict__ Brow = Bm + (kE + e) * K;
            for (int i = HOT; i < cnt; i++) {
                int j = (pw[i >> 2] >> ((i & 3) * 8)) & 0xFF;
                if (j != k) dot += __ldg(Brow + j) * g_dv[j];
            }
        }
        float2 icbz = g_icbz[e];
        float2 buw  = g_buw[kE + e];
        float gkc = sigm_neg(dot) - 1.0f;
        float wk  = icbz.x * (buw.x * gkc + icbz.y);
        acc += buw.y * wk;
    }

    // deterministic block reduction
    __shared__ float warpacc[8];
    int w = tid >> 5, l = tid & 31;
    acc += __shfl_xor_sync(0xFFFFFFFFu, acc, 16);
    acc += __shfl_xor_sync(0xFFFFFFFFu, acc, 8);
    acc += __shfl_xor_sync(0xFFFFFFFFu, acc, 4);
    acc += __shfl_xor_sync(0xFFFFFFFFu, acc, 2);
    acc += __shfl_xor_sync(0xFFFFFFFFu, acc, 1);
    if (l == 0) warpacc[w] = acc;
    __syncthreads();

    __shared__ bool is_last;
    if (tid == 0) {
        float s = 0.0f;
#pragma unroll
        for (int i = 0; i < 8; i++) s += warpacc[i];
        g_partial[k * NBLK + blockIdx.x] = s;
        __threadfence();
        unsigned t = atomicAdd(&g_done[step], 1u);
        is_last = (t == (unsigned)(NBLK * K - 1));
    }
    __syncthreads();
    if (!is_last) return;
    __threadfence();

    // ---- fused epilogue (one block) ----
    __shared__ float s_un[K];
    __shared__ float s_dvn[K];
    __shared__ float red[K];
    if (tid < K) {
        float s = 0.0f;
#pragma unroll
        for (int c = 0; c < NBLK; c++) s += g_partial[tid * NBLK + c];
        float u_old = g_u[tid];
        float u_new = sigm_neg(s);
        float un = g_upd[tid] ? u_new : u_old;
        float ddf = un - u_old;
        red[tid] = ddf * ddf;
        s_un[tid] = un;
        float dvn = un - 0.5f;
        dvn = (fabsf(dvn) > THRESHOLD) ? dvn : 0.0f;
        s_dvn[tid] = dvn;
        g_u[tid] = un;
        g_dv[tid] = dvn;
        if (step == NUM_UPDATE - 2) out[K + tid] = un;  // state_2nd_last
        if (step == NUM_UPDATE - 1) out[tid]     = un;  // state_last
    }
    __syncthreads();
#pragma unroll
    for (int off = 64; off > 0; off >>= 1) {
        if (tid < off && tid + off < K) red[tid] += red[tid + off];
        __syncthreads();
    }
    if (tid == 0) out[2 * K + M + step] = sqrtf(red[0]);

    if (step < NUM_UPDATE - 1) {
        // prepare next-step inputs: dval, Ic
        for (int i = 0; i < E / 256; i++) {
            int e = i * 256 + tid;
            const uint4* pkp = (const uint4*)(g_nzpk + e * MAXNZ);
            uint4 p0 = pkp[0], p1 = pkp[1];
            unsigned pw[8] = {p0.x, p0.y, p0.z, p0.w, p1.x, p1.y, p1.z, p1.w};
            int cnt = g_cnt[e];
            float su = 0.0f;
            float v[HOT];
#pragma unroll
            for (int idx = 0; idx < HOT; idx++) {
                int j = (pw[idx >> 2] >> ((idx & 3) * 8)) & 0xFF;
                bool valid = idx < cnt;
                v[idx] = valid ? s_dvn[j] : 0.0f;
                su += valid ? s_un[j] : 0.0f;
            }
            for (int idx = HOT; idx < cnt; idx++) {
                int j = (pw[idx >> 2] >> ((idx & 3) * 8)) & 0xFF;
                su += s_un[j];
            }
            float4* dst = (float4*)(g_dval + e * HOT);
            dst[0] = make_float4(v[0], v[1], v[2], v[3]);
            dst[1] = make_float4(v[4], v[5], v[6], v[7]);
            float t  = score[e] - su / dd[e];
            float yc = __expf(-t * t);
            float ic = A_emb[3 * e + 0] * (1.0f - gs[2 * e + 0])
                     + A_emb[3 * e + 1] * (1.0f - gs[2 * e + 1])
                     + A_emb[3 * e + 2] * yc;
            g_icbz[e] = make_float2(sigm_neg(ic), g_bz[e]);
        }
    }
}

// ---------------- final predict ----------------
__global__ void predict_kernel(const float* __restrict__ dd,
                               const float* __restrict__ alpha,
                               const float* __restrict__ gamma_e,
                               const int* __restrict__ ex_id,
                               float* __restrict__ out) {
    __shared__ float s_u[K];
    int tid = threadIdx.x;
    if (tid < K) s_u[tid] = g_u[tid];
    __syncthreads();

    int m = blockIdx.x * 256 + tid;
    if (m < M) {
        int e = ex_id[m];
        const uint4* pkp = (const uint4*)(g_nzpk + e * MAXNZ);
        uint4 p0 = pkp[0], p1 = pkp[1];
        unsigned pw[8] = {p0.x, p0.y, p0.z, p0.w, p1.x, p1.y, p1.z, p1.w};
        int cnt = g_cnt[e];
        float accv = 0.0f;
        for (int i = 0; i < cnt; i++) {
            int j = (pw[i >> 2] >> ((i & 3) * 8)) & 0xFF;
            accv += s_u[j];
        }
        float Ukse = accv / dd[e] - 0.5f;
        out[2 * K + m] = sigm_neg(alpha[e] * Ukse + gamma_e[e]);
    }
}

// ---------------- launch ----------------
extern "C" void kernel_launch(void* const* d_in, const int* in_sizes, int n_in,
                              void* d_out, int out_size) {
    const float* U       = (const float*)d_in[0];
    const float* W       = (const float*)d_in[1];
    const float* beta1   = (const float*)d_in[2];
    const float* beta2   = (const float*)d_in[3];
    const float* Bm      = (const float*)d_in[4];
    const float* gs      = (const float*)d_in[5];
    const float* A_emb   = (const float*)d_in[6];
    const float* gamma_c = (const float*)d_in[7];
    const float* gamma_e = (const float*)d_in[8];
    const float* alpha   = (const float*)d_in[9];
    const float* score   = (const float*)d_in[10];
    const float* user    = (const float*)d_in[11];
    const float* q_kn    = (const float*)d_in[12];
    const float* d       = (const float*)d_in[13];
    const int*   stu_id  = (const int*)d_in[14];
    const int*   kn_id   = (const int*)d_in[15];
    const int*   ex_id   = (const int*)d_in[16];
    float* out = (float*)d_out;

    init0_kernel<<<E / 8, 256>>>(q_kn, U, stu_id, kn_id, gamma_c, d, score,
                                 beta2, W, user, gs, A_emb);
    init0b_kernel<<<512, 256>>>(beta1, W, user);
    init1_kernel<<<dim3(NBLK, K), 256>>>(Bm);
    for (int step = 0; step < NUM_UPDATE; ++step) {
        big_kernel<<<dim3(NBLK, K), 256>>>(Bm, d, score, gs, A_emb, out, step);
    }
    predict_kernel<<<(M + 255) / 256, 256>>>(d, alpha, gamma_e, ex_id, out);
}